// round 2
// baseline (speedup 1.0000x reference)
#include <cuda_runtime.h>

#define NN 50000
#define EE 800000
#define ET 850000          // EE + NN self loops
#define F1 128             // HEADS*HID
#define HEADS 8
#define HID 16
#define OUTC 16
#define NEG_SLOPE 0.2f

// ---------------- scratch (device globals; no allocation) ----------------
__device__ float g_h1 [NN * F1];      // layer1 node features (pre-aggregation); reused for h1b after ELU
__device__ float g_out1[NN * F1];     // layer1 aggregation accumulator
__device__ float g_als1[NN * HEADS];
__device__ float g_ald1[NN * HEADS];
__device__ int   g_m1  [NN * HEADS];  // ordered-int max
__device__ float g_den1[NN * HEADS];
__device__ float g_sc1 [ET * HEADS];  // scores -> weights

__device__ float g_h2  [NN * OUTC];
__device__ float g_als2[NN];
__device__ float g_ald2[NN];
__device__ int   g_m2  [NN];
__device__ float g_den2[NN];
__device__ float g_sc2 [ET];

// ---------------- helpers ----------------
__device__ __forceinline__ int f2ord(float f) {
    int i = __float_as_int(f);
    return i >= 0 ? i : (i ^ 0x7fffffff);
}
__device__ __forceinline__ float ord2f(int o) {
    o = o >= 0 ? o : (o ^ 0x7fffffff);
    return __int_as_float(o);
}
// edge_index is int32 (JAX default, x64 disabled)
__device__ __forceinline__ void edge_sd(const int* __restrict__ ei, int e, int& s, int& d) {
    if (e < EE) { s = ei[e]; d = ei[EE + e]; }
    else        { s = e - EE; d = s; }
}

// ---------------- init ----------------
__global__ void k_init(float* __restrict__ out, const float* __restrict__ b2) {
    int i = blockIdx.x * blockDim.x + threadIdx.x;
    if (i < NN * F1)    g_out1[i] = 0.f;
    if (i < NN * HEADS) { g_m1[i] = 0x80000000; g_den1[i] = 0.f; }
    if (i < NN)         { g_m2[i] = 0x80000000; g_den2[i] = 0.f; }
    if (i < NN * OUTC)  out[i] = b2[i & (OUTC - 1)];
}

// ---------------- layer 1: GEMM + attention logits ----------------
// one block (128 thr) per node; thread t owns output feature t
__global__ void k_gemm1(const float* __restrict__ x, const float* __restrict__ W1,
                        const float* __restrict__ a_src, const float* __restrict__ a_dst) {
    int n = blockIdx.x;
    int t = threadIdx.x;
    __shared__ float xs[F1];
    xs[t] = x[n * F1 + t];
    __syncthreads();
    float acc = 0.f;
#pragma unroll 8
    for (int k = 0; k < F1; k++) acc = fmaf(xs[k], W1[k * F1 + t], acc);
    g_h1[n * F1 + t] = acc;
    // per-head logits: reduce groups of 16 lanes
    float ps = acc * a_src[t];
    float pd = acc * a_dst[t];
#pragma unroll
    for (int off = 8; off >= 1; off >>= 1) {
        ps += __shfl_down_sync(0xffffffffu, ps, off);
        pd += __shfl_down_sync(0xffffffffu, pd, off);
    }
    if ((t & 15) == 0) {
        int h = t >> 4;
        g_als1[n * HEADS + h] = ps;
        g_ald1[n * HEADS + h] = pd;
    }
}

// ---------------- layer 1: edge score + segment max ----------------
__global__ void k_edge_max1(const int* __restrict__ ei) {
    int idx = blockIdx.x * blockDim.x + threadIdx.x;
    if (idx >= ET * HEADS) return;
    int e = idx >> 3, h = idx & 7;
    int s, d; edge_sd(ei, e, s, d);
    float sc = g_als1[s * HEADS + h] + g_ald1[d * HEADS + h];
    sc = sc > 0.f ? sc : NEG_SLOPE * sc;
    g_sc1[idx] = sc;
    atomicMax(&g_m1[d * HEADS + h], f2ord(sc));
}

// ---------------- layer 1: exp + segment sum ----------------
__global__ void k_edge_den1(const int* __restrict__ ei) {
    int idx = blockIdx.x * blockDim.x + threadIdx.x;
    if (idx >= ET * HEADS) return;
    int e = idx >> 3, h = idx & 7;
    int s, d; edge_sd(ei, e, s, d);
    float m = ord2f(g_m1[d * HEADS + h]);
    float w = __expf(g_sc1[idx] - m);
    g_sc1[idx] = w;
    atomicAdd(&g_den1[d * HEADS + h], w);
}

// ---------------- layer 1: weighted scatter ----------------
// 128 threads per edge (one per feature); 2 edges per 256-thread block
__global__ void k_scatter1(const int* __restrict__ ei) {
    int e = blockIdx.x * 2 + (threadIdx.x >> 7);
    if (e >= ET) return;
    int t = threadIdx.x & 127;
    int s, d; edge_sd(ei, e, s, d);
    int h = t >> 4;
    float alpha = g_sc1[e * HEADS + h] / g_den1[d * HEADS + h];
    float v = g_h1[s * F1 + t] * alpha;
    atomicAdd(&g_out1[d * F1 + t], v);
}

// ---------------- layer 1 epilogue: bias + ELU (writes back into g_h1) ----------------
__global__ void k_elu(const float* __restrict__ b1) {
    int i = blockIdx.x * blockDim.x + threadIdx.x;
    if (i >= NN * F1) return;
    float v = g_out1[i] + b1[i & (F1 - 1)];
    g_h1[i] = v > 0.f ? v : (expf(v) - 1.f);
}

// ---------------- layer 2: GEMM + logits ----------------
// 128 threads = 8 rows x 16 cols per block
__global__ void k_gemm2(const float* __restrict__ W2,
                        const float* __restrict__ a_src, const float* __restrict__ a_dst) {
    int t = threadIdx.x;
    int row = blockIdx.x * 8 + (t >> 4);
    int col = t & 15;
    if (row >= NN) return;
    const float* rp = g_h1 + row * F1;
    float acc = 0.f;
#pragma unroll 8
    for (int k = 0; k < F1; k++) acc = fmaf(rp[k], W2[k * OUTC + col], acc);
    g_h2[row * OUTC + col] = acc;
    float ps = acc * a_src[col];
    float pd = acc * a_dst[col];
#pragma unroll
    for (int off = 8; off >= 1; off >>= 1) {
        ps += __shfl_down_sync(0xffffffffu, ps, off);
        pd += __shfl_down_sync(0xffffffffu, pd, off);
    }
    if (col == 0) { g_als2[row] = ps; g_ald2[row] = pd; }
}

// ---------------- layer 2 edge kernels (H=1) ----------------
__global__ void k_edge_max2(const int* __restrict__ ei) {
    int e = blockIdx.x * blockDim.x + threadIdx.x;
    if (e >= ET) return;
    int s, d; edge_sd(ei, e, s, d);
    float sc = g_als2[s] + g_ald2[d];
    sc = sc > 0.f ? sc : NEG_SLOPE * sc;
    g_sc2[e] = sc;
    atomicMax(&g_m2[d], f2ord(sc));
}

__global__ void k_edge_den2(const int* __restrict__ ei) {
    int e = blockIdx.x * blockDim.x + threadIdx.x;
    if (e >= ET) return;
    int s, d; edge_sd(ei, e, s, d);
    float w = __expf(g_sc2[e] - ord2f(g_m2[d]));
    g_sc2[e] = w;
    atomicAdd(&g_den2[d], w);
}

// 16 threads per edge
__global__ void k_scatter2(const int* __restrict__ ei, float* __restrict__ out) {
    int idx = blockIdx.x * blockDim.x + threadIdx.x;
    if (idx >= ET * OUTC) return;
    int e = idx >> 4, c = idx & 15;
    int s, d; edge_sd(ei, e, s, d);
    float alpha = g_sc2[e] / g_den2[d];
    atomicAdd(&out[d * OUTC + c], g_h2[s * OUTC + c] * alpha);
}

// ---------------- launch ----------------
extern "C" void kernel_launch(void* const* d_in, const int* in_sizes, int n_in,
                              void* d_out, int out_size) {
    const float* x   = (const float*)d_in[0];
    const int*   ei  = (const int*)d_in[1];
    const float* W1  = (const float*)d_in[2];
    const float* as1 = (const float*)d_in[3];
    const float* ad1 = (const float*)d_in[4];
    const float* b1  = (const float*)d_in[5];
    const float* W2  = (const float*)d_in[6];
    const float* as2 = (const float*)d_in[7];
    const float* ad2 = (const float*)d_in[8];
    const float* b2  = (const float*)d_in[9];
    float* out = (float*)d_out;

    k_init<<<(NN * F1 + 255) / 256, 256>>>(out, b2);
    k_gemm1<<<NN, 128>>>(x, W1, as1, ad1);
    k_edge_max1<<<(ET * HEADS + 255) / 256, 256>>>(ei);
    k_edge_den1<<<(ET * HEADS + 255) / 256, 256>>>(ei);
    k_scatter1<<<(ET + 1) / 2, 256>>>(ei);
    k_elu<<<(NN * F1 + 255) / 256, 256>>>(b1);
    k_gemm2<<<(NN + 7) / 8, 128>>>(W2, as2, ad2);
    k_edge_max2<<<(ET + 255) / 256, 256>>>(ei);
    k_edge_den2<<<(ET + 255) / 256, 256>>>(ei);
    k_scatter2<<<(ET * OUTC + 255) / 256, 256>>>(ei, out);
}

// round 3
// speedup vs baseline: 1.9211x; 1.9211x over previous
#include <cuda_runtime.h>
#include <math.h>

#define NN 50000
#define EE 800000
#define ET 850000          // EE + NN self loops
#define F1 128             // HEADS*HID
#define HEADS 8
#define HID 16
#define OUTC 16
#define NEG_SLOPE 0.2f

// ---------------- scratch ----------------
__device__ float g_h1 [NN * F1];
__device__ float g_out1[NN * F1];
__device__ float g_als1[NN * HEADS];
__device__ float g_ald1[NN * HEADS];
__device__ float g_h2 [NN * OUTC];
__device__ float g_als2[NN];
__device__ float g_ald2[NN];
__device__ int   g_cnt[NN];
__device__ int   g_off[NN + 1];
__device__ int   g_cur[NN];
__device__ int   g_csr[ET];           // src node id per CSR slot (grouped by dst)

__device__ __forceinline__ void edge_sd(const int* __restrict__ ei, int e, int& s, int& d) {
    if (e < EE) { s = ei[e]; d = ei[EE + e]; }
    else        { s = e - EE; d = s; }
}

// ---------------- CSR build ----------------
__global__ void k_zero() {
    int i = blockIdx.x * blockDim.x + threadIdx.x;
    if (i < NN) g_cnt[i] = 0;
}

__global__ void k_hist(const int* __restrict__ ei) {
    int e = blockIdx.x * blockDim.x + threadIdx.x;
    if (e >= ET) return;
    int s, d; edge_sd(ei, e, s, d);
    atomicAdd(&g_cnt[d], 1);
}

__global__ void k_scan() {
    const int CH = (NN + 1023) / 1024;   // 49
    int t = threadIdx.x;
    int base = t * CH;
    int sum = 0;
    for (int i = 0; i < CH; i++) {
        int idx = base + i;
        if (idx < NN) sum += g_cnt[idx];
    }
    __shared__ int ps[1024];
    ps[t] = sum;
    __syncthreads();
    for (int off = 1; off < 1024; off <<= 1) {
        int v = (t >= off) ? ps[t - off] : 0;
        __syncthreads();
        ps[t] += v;
        __syncthreads();
    }
    int run = ps[t] - sum;  // exclusive prefix
    for (int i = 0; i < CH; i++) {
        int idx = base + i;
        if (idx < NN) {
            g_off[idx] = run;
            g_cur[idx] = run;
            run += g_cnt[idx];
        }
    }
    if (t == 1023) g_off[NN] = ps[1023];
}

__global__ void k_fill(const int* __restrict__ ei) {
    int e = blockIdx.x * blockDim.x + threadIdx.x;
    if (e >= ET) return;
    int s, d; edge_sd(ei, e, s, d);
    int pos = atomicAdd(&g_cur[d], 1);
    g_csr[pos] = s;
}

// ---------------- layer 1: GEMM (8 nodes/block) + fused logits ----------------
__global__ void k_gemm1(const float* __restrict__ x, const float* __restrict__ W1,
                        const float* __restrict__ as1, const float* __restrict__ ad1) {
    int nb = blockIdx.x * 8;
    int t = threadIdx.x;                 // 128
    __shared__ float4 xs[8][32];
    const float4* xv = (const float4*)(x + nb * F1);
    ((float4*)xs)[t]       = xv[t];
    ((float4*)xs)[t + 128] = xv[t + 128];
    __syncthreads();
    float acc[8] = {0.f,0.f,0.f,0.f,0.f,0.f,0.f,0.f};
#pragma unroll 4
    for (int k4 = 0; k4 < 32; k4++) {
        float w0 = W1[(k4 * 4 + 0) * F1 + t];
        float w1 = W1[(k4 * 4 + 1) * F1 + t];
        float w2 = W1[(k4 * 4 + 2) * F1 + t];
        float w3 = W1[(k4 * 4 + 3) * F1 + t];
#pragma unroll
        for (int j = 0; j < 8; j++) {
            float4 xj = xs[j][k4];
            acc[j] = fmaf(xj.x, w0, acc[j]);
            acc[j] = fmaf(xj.y, w1, acc[j]);
            acc[j] = fmaf(xj.z, w2, acc[j]);
            acc[j] = fmaf(xj.w, w3, acc[j]);
        }
    }
    float as = as1[t], ad = ad1[t];
#pragma unroll
    for (int j = 0; j < 8; j++) {
        g_h1[(nb + j) * F1 + t] = acc[j];
        float p = acc[j] * as, q = acc[j] * ad;
#pragma unroll
        for (int off = 8; off >= 1; off >>= 1) {
            p += __shfl_down_sync(0xffffffffu, p, off, 16);
            q += __shfl_down_sync(0xffffffffu, q, off, 16);
        }
        if ((t & 15) == 0) {
            g_als1[(nb + j) * HEADS + (t >> 4)] = p;
            g_ald1[(nb + j) * HEADS + (t >> 4)] = q;
        }
    }
}

// ---------------- layer 1: gather aggregation (no atomics) ----------------
// one block (128 thr) per dst node; thread t = head (t>>4), channel (t&15)
__global__ void k_agg1() {
    int d = blockIdx.x;
    int t = threadIdx.x;
    int h = t >> 4, c = t & 15;
    unsigned hm = 0xFFFFu << (t & 16);
    int beg = g_off[d], end = g_off[d + 1];
    float ald = g_ald1[d * HEADS + h];
    // pass A: per-head max
    float m = -1e30f;
    for (int i = beg + c; i < end; i += 16) {
        int s = g_csr[i];
        float sc = g_als1[s * HEADS + h] + ald;
        sc = sc > 0.f ? sc : NEG_SLOPE * sc;
        m = fmaxf(m, sc);
    }
#pragma unroll
    for (int off = 8; off >= 1; off >>= 1)
        m = fmaxf(m, __shfl_xor_sync(hm, m, off, 16));
    // pass B: weighted accumulate
    float acc = 0.f, den = 0.f;
    for (int i = beg; i < end; i++) {
        int s = g_csr[i];
        float w = 0.f;
        if (c == 0) {
            float sc = g_als1[s * HEADS + h] + ald;
            sc = sc > 0.f ? sc : NEG_SLOPE * sc;
            w = __expf(sc - m);
        }
        w = __shfl_sync(hm, w, t & 16);
        den += w;
        acc = fmaf(w, g_h1[s * F1 + t], acc);
    }
    g_out1[d * F1 + t] = acc / den;
}

// ---------------- ELU ----------------
__global__ void k_elu(const float* __restrict__ b1) {
    int i = blockIdx.x * blockDim.x + threadIdx.x;
    if (i >= NN * F1) return;
    float v = g_out1[i] + b1[i & (F1 - 1)];
    g_h1[i] = v > 0.f ? v : expm1f(v);
}

// ---------------- layer 2: GEMM (8 rows x 16 cols per block) + logits ----------------
__global__ void k_gemm2(const float* __restrict__ W2,
                        const float* __restrict__ as2, const float* __restrict__ ad2) {
    int t = threadIdx.x;                  // 128
    int r = blockIdx.x * 8 + (t >> 4);
    int c = t & 15;
    __shared__ float ws[F1][OUTC];
    for (int i = t; i < F1 * OUTC; i += 128) ws[i / OUTC][i % OUTC] = W2[i];
    __syncthreads();
    const float4* h4 = (const float4*)(g_h1 + r * F1);
    float acc = 0.f;
#pragma unroll 8
    for (int k4 = 0; k4 < 32; k4++) {
        float4 hv = h4[k4];
        acc = fmaf(hv.x, ws[k4 * 4 + 0][c], acc);
        acc = fmaf(hv.y, ws[k4 * 4 + 1][c], acc);
        acc = fmaf(hv.z, ws[k4 * 4 + 2][c], acc);
        acc = fmaf(hv.w, ws[k4 * 4 + 3][c], acc);
    }
    g_h2[r * OUTC + c] = acc;
    float p = acc * as2[c], q = acc * ad2[c];
#pragma unroll
    for (int off = 8; off >= 1; off >>= 1) {
        p += __shfl_down_sync(0xffffffffu, p, off, 16);
        q += __shfl_down_sync(0xffffffffu, q, off, 16);
    }
    if (c == 0) { g_als2[r] = p; g_ald2[r] = q; }
}

// ---------------- layer 2: gather aggregation ----------------
// 128 thr = 8 nodes x 16 channels
__global__ void k_agg2(const float* __restrict__ b2, float* __restrict__ out) {
    int t = threadIdx.x;
    int d = blockIdx.x * 8 + (t >> 4);
    int c = t & 15;
    unsigned hm = 0xFFFFu << (t & 16);
    int beg = g_off[d], end = g_off[d + 1];
    float ald = g_ald2[d];
    float m = -1e30f;
    for (int i = beg + c; i < end; i += 16) {
        int s = g_csr[i];
        float sc = g_als2[s] + ald;
        sc = sc > 0.f ? sc : NEG_SLOPE * sc;
        m = fmaxf(m, sc);
    }
#pragma unroll
    for (int off = 8; off >= 1; off >>= 1)
        m = fmaxf(m, __shfl_xor_sync(hm, m, off, 16));
    float acc = 0.f, den = 0.f;
    for (int i = beg; i < end; i++) {
        int s = g_csr[i];
        float w = 0.f;
        if (c == 0) {
            float sc = g_als2[s] + ald;
            sc = sc > 0.f ? sc : NEG_SLOPE * sc;
            w = __expf(sc - m);
        }
        w = __shfl_sync(hm, w, t & 16);
        den += w;
        acc = fmaf(w, g_h2[s * OUTC + c], acc);
    }
    out[d * OUTC + c] = acc / den + b2[c];
}

// ---------------- launch ----------------
extern "C" void kernel_launch(void* const* d_in, const int* in_sizes, int n_in,
                              void* d_out, int out_size) {
    const float* x   = (const float*)d_in[0];
    const int*   ei  = (const int*)d_in[1];
    const float* W1  = (const float*)d_in[2];
    const float* as1 = (const float*)d_in[3];
    const float* ad1 = (const float*)d_in[4];
    const float* b1  = (const float*)d_in[5];
    const float* W2  = (const float*)d_in[6];
    const float* as2 = (const float*)d_in[7];
    const float* ad2 = (const float*)d_in[8];
    const float* b2  = (const float*)d_in[9];
    float* out = (float*)d_out;

    k_zero<<<(NN + 255) / 256, 256>>>();
    k_hist<<<(ET + 255) / 256, 256>>>(ei);
    k_scan<<<1, 1024>>>();
    k_fill<<<(ET + 255) / 256, 256>>>(ei);
    k_gemm1<<<NN / 8, 128>>>(x, W1, as1, ad1);
    k_agg1<<<NN, 128>>>();
    k_elu<<<(NN * F1 + 255) / 256, 256>>>(b1);
    k_gemm2<<<NN / 8, 128>>>(W2, as2, ad2);
    k_agg2<<<NN / 8, 128>>>(b2, out);
}

// round 4
// speedup vs baseline: 2.1210x; 1.1041x over previous
#include <cuda_runtime.h>
#include <math.h>

#define NN 50000
#define EE 800000
#define ET 850000
#define F1 128
#define HEADS 8
#define HID 16
#define OUTC 16
#define NEG_SLOPE 0.2f

// ---------------- scratch ----------------
__device__ float g_h1 [NN * F1];     // layer1 pre-aggregation features
__device__ float g_out1[NN * F1];    // layer1 output after softmax-agg + bias + ELU
__device__ float g_als1[NN * HEADS];
__device__ float g_ald1[NN * HEADS];
__device__ float g_h2 [NN * OUTC];
__device__ float g_als2[NN];
__device__ float g_ald2[NN];
__device__ int   g_cnt[NN];
__device__ int   g_off[NN + 1];
__device__ int   g_cur[NN];
__device__ int   g_csr[ET];          // src ids grouped by dst

// ---------------- CSR build ----------------
// self-loop pre-counted: cnt starts at 1
__global__ void k_zero() {
    int i = blockIdx.x * blockDim.x + threadIdx.x;
    if (i < NN) g_cnt[i] = 1;
}

// histogram over real edges, int4 vectorized (EE % 4 == 0)
__global__ void k_hist(const int* __restrict__ ei) {
    int i = blockIdx.x * blockDim.x + threadIdx.x;
    if (i >= EE / 4) return;
    int4 d4 = ((const int4*)(ei + EE))[i];
    atomicAdd(&g_cnt[d4.x], 1);
    atomicAdd(&g_cnt[d4.y], 1);
    atomicAdd(&g_cnt[d4.z], 1);
    atomicAdd(&g_cnt[d4.w], 1);
}

__global__ void k_scan() {
    const int CH = (NN + 1023) / 1024;
    int t = threadIdx.x;
    int base = t * CH;
    int sum = 0;
    for (int i = 0; i < CH; i++) {
        int idx = base + i;
        if (idx < NN) sum += g_cnt[idx];
    }
    __shared__ int ps[1024];
    ps[t] = sum;
    __syncthreads();
    for (int off = 1; off < 1024; off <<= 1) {
        int v = (t >= off) ? ps[t - off] : 0;
        __syncthreads();
        ps[t] += v;
        __syncthreads();
    }
    int run = ps[t] - sum;
    for (int i = 0; i < CH; i++) {
        int idx = base + i;
        if (idx < NN) {
            g_off[idx] = run;
            // self loop occupies first slot; g_cur starts after it
            g_csr[run] = idx;
            g_cur[idx] = run + 1;
            run += g_cnt[idx];
        }
    }
    if (t == 1023) g_off[NN] = ps[1023];
}

// fill real edges, 4 independent chains per thread
__global__ void k_fill(const int* __restrict__ ei) {
    int base = (blockIdx.x * blockDim.x + threadIdx.x) * 4;
    if (base >= EE) return;
#pragma unroll
    for (int k = 0; k < 4; k++) {
        int e = base + k;
        if (e < EE) {
            int s = ei[e], d = ei[EE + e];
            int pos = atomicAdd(&g_cur[d], 1);
            g_csr[pos] = s;
        }
    }
}

// ---------------- layer 1: GEMM (8 nodes/block) + fused logits ----------------
__global__ void k_gemm1(const float* __restrict__ x, const float* __restrict__ W1,
                        const float* __restrict__ as1, const float* __restrict__ ad1) {
    int nb = blockIdx.x * 8;
    int t = threadIdx.x;                 // 128
    __shared__ float4 xs[8][32];
    const float4* xv = (const float4*)(x + nb * F1);
    ((float4*)xs)[t]       = xv[t];
    ((float4*)xs)[t + 128] = xv[t + 128];
    __syncthreads();
    float acc[8] = {0.f,0.f,0.f,0.f,0.f,0.f,0.f,0.f};
#pragma unroll 4
    for (int k4 = 0; k4 < 32; k4++) {
        float w0 = W1[(k4 * 4 + 0) * F1 + t];
        float w1 = W1[(k4 * 4 + 1) * F1 + t];
        float w2 = W1[(k4 * 4 + 2) * F1 + t];
        float w3 = W1[(k4 * 4 + 3) * F1 + t];
#pragma unroll
        for (int j = 0; j < 8; j++) {
            float4 xj = xs[j][k4];
            acc[j] = fmaf(xj.x, w0, acc[j]);
            acc[j] = fmaf(xj.y, w1, acc[j]);
            acc[j] = fmaf(xj.z, w2, acc[j]);
            acc[j] = fmaf(xj.w, w3, acc[j]);
        }
    }
    float as = as1[t], ad = ad1[t];
#pragma unroll
    for (int j = 0; j < 8; j++) {
        g_h1[(nb + j) * F1 + t] = acc[j];
        float p = acc[j] * as, q = acc[j] * ad;
#pragma unroll
        for (int off = 8; off >= 1; off >>= 1) {
            p += __shfl_down_sync(0xffffffffu, p, off, 16);
            q += __shfl_down_sync(0xffffffffu, q, off, 16);
        }
        if ((t & 15) == 0) {
            g_als1[(nb + j) * HEADS + (t >> 4)] = p;
            g_ald1[(nb + j) * HEADS + (t >> 4)] = q;
        }
    }
}

// ---------------- layer 1: gather softmax-agg, single pass (no max), batched MLP=16 ----------------
// one block per dst node, 128 thr; group = head (t>>4), lane c = t&15
__global__ void k_agg1(const float* __restrict__ b1) {
    int d = blockIdx.x;
    int t = threadIdx.x;
    int h = t >> 4, c = t & 15;
    unsigned hm = 0xFFFFu << (t & 16);
    int beg = g_off[d], end = g_off[d + 1];
    float ald = g_ald1[d * HEADS + h];
    float acc = 0.f, den = 0.f;
    for (int i0 = beg; i0 < end; i0 += 16) {
        int i = i0 + c;
        int s = 0; float w = 0.f;
        if (i < end) {
            s = g_csr[i];
            float sc = g_als1[s * HEADS + h] + ald;
            sc = sc > 0.f ? sc : NEG_SLOPE * sc;
            w = __expf(sc);
        }
        int lim = min(16, end - i0);        // block-uniform
#pragma unroll 4
        for (int j = 0; j < lim; j++) {
            int   sj = __shfl_sync(hm, s, j, 16);
            float wj = __shfl_sync(hm, w, j, 16);
            den += wj;
            acc = fmaf(wj, g_h1[sj * F1 + t], acc);
        }
    }
    float v = acc / den + b1[t];
    g_out1[d * F1 + t] = v > 0.f ? v : expm1f(v);
}

// ---------------- layer 2: GEMM (8 rows x 16 cols per block) + logits ----------------
__global__ void k_gemm2(const float* __restrict__ W2,
                        const float* __restrict__ as2, const float* __restrict__ ad2) {
    int t = threadIdx.x;
    int r = blockIdx.x * 8 + (t >> 4);
    int c = t & 15;
    __shared__ float ws[F1][OUTC];
    for (int i = t; i < F1 * OUTC; i += 128) ws[i / OUTC][i % OUTC] = W2[i];
    __syncthreads();
    const float4* h4 = (const float4*)(g_out1 + r * F1);
    float acc = 0.f;
#pragma unroll 8
    for (int k4 = 0; k4 < 32; k4++) {
        float4 hv = h4[k4];
        acc = fmaf(hv.x, ws[k4 * 4 + 0][c], acc);
        acc = fmaf(hv.y, ws[k4 * 4 + 1][c], acc);
        acc = fmaf(hv.z, ws[k4 * 4 + 2][c], acc);
        acc = fmaf(hv.w, ws[k4 * 4 + 3][c], acc);
    }
    g_h2[r * OUTC + c] = acc;
    float p = acc * as2[c], q = acc * ad2[c];
#pragma unroll
    for (int off = 8; off >= 1; off >>= 1) {
        p += __shfl_down_sync(0xffffffffu, p, off, 16);
        q += __shfl_down_sync(0xffffffffu, q, off, 16);
    }
    if (c == 0) { g_als2[r] = p; g_ald2[r] = q; }
}

// ---------------- layer 2: gather softmax-agg, single pass ----------------
// 128 thr = 8 nodes x 16 channels; group = node
__global__ void k_agg2(const float* __restrict__ b2, float* __restrict__ out) {
    int t = threadIdx.x;
    int d = blockIdx.x * 8 + (t >> 4);
    int c = t & 15;
    unsigned hm = 0xFFFFu << (t & 16);
    int beg = g_off[d], end = g_off[d + 1];
    float ald = g_ald2[d];
    float acc = 0.f, den = 0.f;
    for (int i0 = beg; i0 < end; i0 += 16) {
        int i = i0 + c;
        int s = 0; float w = 0.f;
        if (i < end) {
            s = g_csr[i];
            float sc = g_als2[s] + ald;
            sc = sc > 0.f ? sc : NEG_SLOPE * sc;
            w = __expf(sc);
        }
        int lim = min(16, end - i0);        // group-uniform
#pragma unroll 4
        for (int j = 0; j < lim; j++) {
            int   sj = __shfl_sync(hm, s, j, 16);
            float wj = __shfl_sync(hm, w, j, 16);
            den += wj;
            acc = fmaf(wj, g_h2[sj * OUTC + c], acc);
        }
    }
    out[d * OUTC + c] = acc / den + b2[c];
}

// ---------------- launch ----------------
extern "C" void kernel_launch(void* const* d_in, const int* in_sizes, int n_in,
                              void* d_out, int out_size) {
    const float* x   = (const float*)d_in[0];
    const int*   ei  = (const int*)d_in[1];
    const float* W1  = (const float*)d_in[2];
    const float* as1 = (const float*)d_in[3];
    const float* ad1 = (const float*)d_in[4];
    const float* b1  = (const float*)d_in[5];
    const float* W2  = (const float*)d_in[6];
    const float* as2 = (const float*)d_in[7];
    const float* ad2 = (const float*)d_in[8];
    const float* b2  = (const float*)d_in[9];
    float* out = (float*)d_out;

    k_zero<<<(NN + 255) / 256, 256>>>();
    k_hist<<<(EE / 4 + 255) / 256, 256>>>(ei);
    k_scan<<<1, 1024>>>();
    k_fill<<<(EE / 4 + 255) / 256, 256>>>(ei);
    k_gemm1<<<NN / 8, 128>>>(x, W1, as1, ad1);
    k_agg1<<<NN, 128>>>(b1);
    k_gemm2<<<NN / 8, 128>>>(W2, as2, ad2);
    k_agg2<<<NN / 8, 128>>>(b2, out);
}

// round 5
// speedup vs baseline: 2.3368x; 1.1017x over previous
#include <cuda_runtime.h>
#include <math.h>

#define NN 50000
#define EE 800000
#define ET 850000
#define F1 128
#define HEADS 8
#define HID 16
#define OUTC 16
#define NEG_SLOPE 0.2f

// ---------------- scratch ----------------
__device__ __align__(16) float g_h1 [NN * F1];
__device__ __align__(16) float g_out1[NN * F1];
__device__ float g_als1[NN * HEADS];
__device__ float g_ald1[NN * HEADS];
__device__ __align__(16) float g_h2 [NN * OUTC];
__device__ float g_als2[NN];
__device__ float g_ald2[NN];
__device__ int   g_cnt[NN];
__device__ int   g_off[NN + 1];
__device__ int   g_cur[NN];
__device__ int   g_csr[ET];

// ---------------- CSR build ----------------
__global__ void k_zero() {
    int i = blockIdx.x * blockDim.x + threadIdx.x;
    if (i < NN) g_cnt[i] = 1;            // self loop pre-counted
}

__global__ void k_hist(const int* __restrict__ ei) {
    int i = blockIdx.x * blockDim.x + threadIdx.x;
    if (i >= EE / 4) return;
    int4 d4 = ((const int4*)(ei + EE))[i];
    atomicAdd(&g_cnt[d4.x], 1);
    atomicAdd(&g_cnt[d4.y], 1);
    atomicAdd(&g_cnt[d4.z], 1);
    atomicAdd(&g_cnt[d4.w], 1);
}

__global__ void k_scan() {
    const int CH = (NN + 1023) / 1024;
    int t = threadIdx.x;
    int base = t * CH;
    int sum = 0;
    for (int i = 0; i < CH; i++) {
        int idx = base + i;
        if (idx < NN) sum += g_cnt[idx];
    }
    __shared__ int ps[1024];
    ps[t] = sum;
    __syncthreads();
    for (int off = 1; off < 1024; off <<= 1) {
        int v = (t >= off) ? ps[t - off] : 0;
        __syncthreads();
        ps[t] += v;
        __syncthreads();
    }
    int run = ps[t] - sum;
    for (int i = 0; i < CH; i++) {
        int idx = base + i;
        if (idx < NN) {
            g_off[idx] = run;
            g_csr[run] = idx;            // self loop in slot 0
            g_cur[idx] = run + 1;
            run += g_cnt[idx];
        }
    }
    if (t == 1023) g_off[NN] = ps[1023];
}

__global__ void k_fill(const int* __restrict__ ei) {
    int base = (blockIdx.x * blockDim.x + threadIdx.x) * 4;
    if (base >= EE) return;
#pragma unroll
    for (int k = 0; k < 4; k++) {
        int e = base + k;
        if (e < EE) {
            int s = ei[e], d = ei[EE + e];
            int pos = atomicAdd(&g_cur[d], 1);
            g_csr[pos] = s;
        }
    }
}

// ---------------- layer 1: GEMM (8 nodes/block) + fused logits ----------------
__global__ void k_gemm1(const float* __restrict__ x, const float* __restrict__ W1,
                        const float* __restrict__ as1, const float* __restrict__ ad1) {
    int nb = blockIdx.x * 8;
    int t = threadIdx.x;                 // 128
    __shared__ float4 xs[8][32];
    const float4* xv = (const float4*)(x + nb * F1);
    ((float4*)xs)[t]       = xv[t];
    ((float4*)xs)[t + 128] = xv[t + 128];
    __syncthreads();
    float acc[8] = {0.f,0.f,0.f,0.f,0.f,0.f,0.f,0.f};
#pragma unroll 4
    for (int k4 = 0; k4 < 32; k4++) {
        float w0 = W1[(k4 * 4 + 0) * F1 + t];
        float w1 = W1[(k4 * 4 + 1) * F1 + t];
        float w2 = W1[(k4 * 4 + 2) * F1 + t];
        float w3 = W1[(k4 * 4 + 3) * F1 + t];
#pragma unroll
        for (int j = 0; j < 8; j++) {
            float4 xj = xs[j][k4];
            acc[j] = fmaf(xj.x, w0, acc[j]);
            acc[j] = fmaf(xj.y, w1, acc[j]);
            acc[j] = fmaf(xj.z, w2, acc[j]);
            acc[j] = fmaf(xj.w, w3, acc[j]);
        }
    }
    float as = as1[t], ad = ad1[t];
#pragma unroll
    for (int j = 0; j < 8; j++) {
        g_h1[(nb + j) * F1 + t] = acc[j];
        float p = acc[j] * as, q = acc[j] * ad;
#pragma unroll
        for (int off = 8; off >= 1; off >>= 1) {
            p += __shfl_down_sync(0xffffffffu, p, off, 16);
            q += __shfl_down_sync(0xffffffffu, q, off, 16);
        }
        if ((t & 15) == 0) {
            g_als1[(nb + j) * HEADS + (t >> 4)] = p;
            g_ald1[(nb + j) * HEADS + (t >> 4)] = q;
        }
    }
}

// ---------------- layer 1: aggregation, one WARP per dst node ----------------
// lane l owns channels [4l, 4l+4); head h = l>>2
__global__ void k_agg1(const float* __restrict__ b1) {
    int warp = threadIdx.x >> 5;
    int lane = threadIdx.x & 31;
    int d = blockIdx.x * 8 + warp;
    if (d >= NN) return;
    int h = lane >> 2;
    int beg = g_off[d], end = g_off[d + 1];
    float ald = g_ald1[d * HEADS + h];
    float4 acc = {0.f, 0.f, 0.f, 0.f};
    float den = 0.f;
    for (int i0 = beg; i0 < end; i0 += 32) {
        int i = i0 + lane;
        int s = (i < end) ? g_csr[i] : 0;
        int lim = min(32, end - i0);
#pragma unroll 4
        for (int j = 0; j < lim; j++) {
            int sj = __shfl_sync(0xffffffffu, s, j);
            float al = g_als1[sj * HEADS + h] + ald;
            al = al > 0.f ? al : NEG_SLOPE * al;
            float w = __expf(al);
            den += w;
            float4 hv = *(const float4*)(g_h1 + sj * F1 + lane * 4);
            acc.x = fmaf(w, hv.x, acc.x);
            acc.y = fmaf(w, hv.y, acc.y);
            acc.z = fmaf(w, hv.z, acc.z);
            acc.w = fmaf(w, hv.w, acc.w);
        }
    }
    float inv = 1.f / den;
    float4 bv = *(const float4*)(b1 + lane * 4);
    float4 o;
    o.x = acc.x * inv + bv.x;
    o.y = acc.y * inv + bv.y;
    o.z = acc.z * inv + bv.z;
    o.w = acc.w * inv + bv.w;
    o.x = o.x > 0.f ? o.x : expm1f(o.x);
    o.y = o.y > 0.f ? o.y : expm1f(o.y);
    o.z = o.z > 0.f ? o.z : expm1f(o.z);
    o.w = o.w > 0.f ? o.w : expm1f(o.w);
    *(float4*)(g_out1 + d * F1 + lane * 4) = o;
}

// ---------------- layer 2: GEMM (8 rows x 16 cols per block) + logits ----------------
__global__ void k_gemm2(const float* __restrict__ W2,
                        const float* __restrict__ as2, const float* __restrict__ ad2) {
    int t = threadIdx.x;
    int r = blockIdx.x * 8 + (t >> 4);
    int c = t & 15;
    __shared__ float ws[F1][OUTC];
    for (int i = t; i < F1 * OUTC; i += 128) ws[i / OUTC][i % OUTC] = W2[i];
    __syncthreads();
    const float4* h4 = (const float4*)(g_out1 + r * F1);
    float acc = 0.f;
#pragma unroll 8
    for (int k4 = 0; k4 < 32; k4++) {
        float4 hv = h4[k4];
        acc = fmaf(hv.x, ws[k4 * 4 + 0][c], acc);
        acc = fmaf(hv.y, ws[k4 * 4 + 1][c], acc);
        acc = fmaf(hv.z, ws[k4 * 4 + 2][c], acc);
        acc = fmaf(hv.w, ws[k4 * 4 + 3][c], acc);
    }
    g_h2[r * OUTC + c] = acc;
    float p = acc * as2[c], q = acc * ad2[c];
#pragma unroll
    for (int off = 8; off >= 1; off >>= 1) {
        p += __shfl_down_sync(0xffffffffu, p, off, 16);
        q += __shfl_down_sync(0xffffffffu, q, off, 16);
    }
    if (c == 0) { g_als2[r] = p; g_ald2[r] = q; }
}

// ---------------- layer 2: aggregation, 16-lane group per dst node ----------------
// block 256 thr = 16 nodes; lanes 0-15 / 16-31 of each warp handle one node each
__global__ void k_agg2(const float* __restrict__ b2, float* __restrict__ out) {
    int t = threadIdx.x;
    int d = blockIdx.x * 16 + (t >> 4);
    if (d >= NN) return;
    int c = t & 15;
    unsigned hm = 0xFFFFu << (t & 16);
    int beg = g_off[d], end = g_off[d + 1];
    float ald = g_ald2[d];
    float acc = 0.f, den = 0.f;
    for (int i0 = beg; i0 < end; i0 += 16) {
        int i = i0 + c;
        int s = (i < end) ? g_csr[i] : 0;
        int lim = min(16, end - i0);
#pragma unroll 4
        for (int j = 0; j < lim; j++) {
            int sj = __shfl_sync(hm, s, j, 16);
            float al = g_als2[sj] + ald;
            al = al > 0.f ? al : NEG_SLOPE * al;
            float w = __expf(al);
            den += w;
            acc = fmaf(w, g_h2[sj * OUTC + c], acc);
        }
    }
    out[d * OUTC + c] = acc / den + b2[c];
}

// ---------------- launch ----------------
extern "C" void kernel_launch(void* const* d_in, const int* in_sizes, int n_in,
                              void* d_out, int out_size) {
    const float* x   = (const float*)d_in[0];
    const int*   ei  = (const int*)d_in[1];
    const float* W1  = (const float*)d_in[2];
    const float* as1 = (const float*)d_in[3];
    const float* ad1 = (const float*)d_in[4];
    const float* b1  = (const float*)d_in[5];
    const float* W2  = (const float*)d_in[6];
    const float* as2 = (const float*)d_in[7];
    const float* ad2 = (const float*)d_in[8];
    const float* b2  = (const float*)d_in[9];
    float* out = (float*)d_out;

    k_zero<<<(NN + 255) / 256, 256>>>();
    k_hist<<<(EE / 4 + 255) / 256, 256>>>(ei);
    k_scan<<<1, 1024>>>();
    k_fill<<<(EE / 4 + 255) / 256, 256>>>(ei);
    k_gemm1<<<NN / 8, 128>>>(x, W1, as1, ad1);
    k_agg1<<<(NN + 7) / 8, 256>>>(b1);
    k_gemm2<<<NN / 8, 128>>>(W2, as2, ad2);
    k_agg2<<<(NN + 15) / 16, 256>>>(b2, out);
}

// round 6
// speedup vs baseline: 2.4205x; 1.0358x over previous
#include <cuda_runtime.h>
#include <math.h>

#define NN 50000
#define EE 800000
#define ET 850000
#define F1 128
#define HEADS 8
#define HID 16
#define OUTC 16
#define NEG_SLOPE 0.2f

// ---------------- scratch ----------------
__device__ __align__(16) float g_h1 [NN * F1];
__device__ __align__(16) float g_out1[NN * F1];
__device__ float g_als1[NN * HEADS];
__device__ float g_ald1[NN * HEADS];
__device__ __align__(16) float g_h2 [NN * OUTC];
__device__ float g_als2[NN];
__device__ float g_ald2[NN];
__device__ int   g_cnt[NN];
__device__ int   g_off[NN + 1];
__device__ int   g_cur[NN];
__device__ int   g_csr[ET];

// ---------------- CSR build ----------------
__global__ void k_zero() {
    int i = blockIdx.x * blockDim.x + threadIdx.x;
    if (i < NN) g_cnt[i] = 1;            // self loop pre-counted
}

__global__ void k_hist(const int* __restrict__ ei) {
    int i = blockIdx.x * blockDim.x + threadIdx.x;
    if (i >= EE / 4) return;
    int4 d4 = ((const int4*)(ei + EE))[i];
    atomicAdd(&g_cnt[d4.x], 1);
    atomicAdd(&g_cnt[d4.y], 1);
    atomicAdd(&g_cnt[d4.z], 1);
    atomicAdd(&g_cnt[d4.w], 1);
}

__global__ void k_scan() {
    const int CH = (NN + 1023) / 1024;
    int t = threadIdx.x;
    int base = t * CH;
    int sum = 0;
    for (int i = 0; i < CH; i++) {
        int idx = base + i;
        if (idx < NN) sum += g_cnt[idx];
    }
    __shared__ int ps[1024];
    ps[t] = sum;
    __syncthreads();
    for (int off = 1; off < 1024; off <<= 1) {
        int v = (t >= off) ? ps[t - off] : 0;
        __syncthreads();
        ps[t] += v;
        __syncthreads();
    }
    int run = ps[t] - sum;
    for (int i = 0; i < CH; i++) {
        int idx = base + i;
        if (idx < NN) {
            g_off[idx] = run;
            g_csr[run] = idx;            // self loop in slot 0
            g_cur[idx] = run + 1;
            run += g_cnt[idx];
        }
    }
    if (t == 1023) g_off[NN] = ps[1023];
}

__global__ void k_fill(const int* __restrict__ ei) {
    int base = (blockIdx.x * blockDim.x + threadIdx.x) * 4;
    if (base >= EE) return;
#pragma unroll
    for (int k = 0; k < 4; k++) {
        int e = base + k;
        if (e < EE) {
            int s = ei[e], d = ei[EE + e];
            int pos = atomicAdd(&g_cur[d], 1);
            g_csr[pos] = s;
        }
    }
}

// ---------------- layer 1: GEMM (8 nodes/block) + fused logits ----------------
__global__ void k_gemm1(const float* __restrict__ x, const float* __restrict__ W1,
                        const float* __restrict__ as1, const float* __restrict__ ad1) {
    int nb = blockIdx.x * 8;
    int t = threadIdx.x;                 // 128
    __shared__ float4 xs[8][32];
    const float4* xv = (const float4*)(x + nb * F1);
    ((float4*)xs)[t]       = xv[t];
    ((float4*)xs)[t + 128] = xv[t + 128];
    __syncthreads();
    float acc[8] = {0.f,0.f,0.f,0.f,0.f,0.f,0.f,0.f};
#pragma unroll 4
    for (int k4 = 0; k4 < 32; k4++) {
        float w0 = W1[(k4 * 4 + 0) * F1 + t];
        float w1 = W1[(k4 * 4 + 1) * F1 + t];
        float w2 = W1[(k4 * 4 + 2) * F1 + t];
        float w3 = W1[(k4 * 4 + 3) * F1 + t];
#pragma unroll
        for (int j = 0; j < 8; j++) {
            float4 xj = xs[j][k4];
            acc[j] = fmaf(xj.x, w0, acc[j]);
            acc[j] = fmaf(xj.y, w1, acc[j]);
            acc[j] = fmaf(xj.z, w2, acc[j]);
            acc[j] = fmaf(xj.w, w3, acc[j]);
        }
    }
    float as = as1[t], ad = ad1[t];
#pragma unroll
    for (int j = 0; j < 8; j++) {
        g_h1[(nb + j) * F1 + t] = acc[j];
        float p = acc[j] * as, q = acc[j] * ad;
#pragma unroll
        for (int off = 8; off >= 1; off >>= 1) {
            p += __shfl_down_sync(0xffffffffu, p, off, 16);
            q += __shfl_down_sync(0xffffffffu, q, off, 16);
        }
        if ((t & 15) == 0) {
            g_als1[(nb + j) * HEADS + (t >> 4)] = p;
            g_ald1[(nb + j) * HEADS + (t >> 4)] = q;
        }
    }
}

// ---------------- layer 1: aggregation, one WARP per dst node ----------------
// lane l owns channels [4l, 4l+4); head h = l>>2
__global__ void k_agg1(const float* __restrict__ b1) {
    int warp = threadIdx.x >> 5;
    int lane = threadIdx.x & 31;
    int d = blockIdx.x * 8 + warp;
    if (d >= NN) return;
    int h = lane >> 2;
    int beg = g_off[d], end = g_off[d + 1];
    float ald = g_ald1[d * HEADS + h];
    float4 acc = {0.f, 0.f, 0.f, 0.f};
    float den = 0.f;
    for (int i0 = beg; i0 < end; i0 += 32) {
        int i = i0 + lane;
        int s = (i < end) ? g_csr[i] : 0;
        int lim = min(32, end - i0);
#pragma unroll 8
        for (int j = 0; j < lim; j++) {
            int sj = __shfl_sync(0xffffffffu, s, j);
            float al = g_als1[sj * HEADS + h] + ald;
            al = al > 0.f ? al : NEG_SLOPE * al;
            float w = __expf(al);
            den += w;
            float4 hv = *(const float4*)(g_h1 + sj * F1 + lane * 4);
            acc.x = fmaf(w, hv.x, acc.x);
            acc.y = fmaf(w, hv.y, acc.y);
            acc.z = fmaf(w, hv.z, acc.z);
            acc.w = fmaf(w, hv.w, acc.w);
        }
    }
    float inv = 1.f / den;
    float4 bv = *(const float4*)(b1 + lane * 4);
    float4 o;
    o.x = acc.x * inv + bv.x;
    o.y = acc.y * inv + bv.y;
    o.z = acc.z * inv + bv.z;
    o.w = acc.w * inv + bv.w;
    o.x = o.x > 0.f ? o.x : expm1f(o.x);
    o.y = o.y > 0.f ? o.y : expm1f(o.y);
    o.z = o.z > 0.f ? o.z : expm1f(o.z);
    o.w = o.w > 0.f ? o.w : expm1f(o.w);
    *(float4*)(g_out1 + d * F1 + lane * 4) = o;
}

// ---------------- layer 2: GEMM, 16 rows/block, smem-staged rows ----------------
// 256 threads: r_loc = t>>4 (16 rows), c = t&15
__global__ void k_gemm2(const float* __restrict__ W2,
                        const float* __restrict__ as2, const float* __restrict__ ad2) {
    int t = threadIdx.x;
    int rbase = blockIdx.x * 16;
    __shared__ float4 sh[16][32];        // 16 rows x 128 floats = 8KB
    __shared__ float ws[F1][OUTC];       // 8KB
    // stage rows: 512 float4, 256 threads -> 2 each
    const float4* src = (const float4*)(g_out1 + rbase * F1);
    ((float4*)sh)[t]       = src[t];
    ((float4*)sh)[t + 256] = src[t + 256];
    // stage W2: 2048 floats, 8 each
#pragma unroll
    for (int i = t; i < F1 * OUTC; i += 256) ws[i >> 4][i & 15] = W2[i];
    __syncthreads();
    int r_loc = t >> 4, c = t & 15;
    float acc = 0.f;
#pragma unroll 8
    for (int k4 = 0; k4 < 32; k4++) {
        float4 hv = sh[r_loc][k4];
        acc = fmaf(hv.x, ws[k4 * 4 + 0][c], acc);
        acc = fmaf(hv.y, ws[k4 * 4 + 1][c], acc);
        acc = fmaf(hv.z, ws[k4 * 4 + 2][c], acc);
        acc = fmaf(hv.w, ws[k4 * 4 + 3][c], acc);
    }
    int r = rbase + r_loc;
    g_h2[r * OUTC + c] = acc;
    float p = acc * as2[c], q = acc * ad2[c];
#pragma unroll
    for (int off = 8; off >= 1; off >>= 1) {
        p += __shfl_down_sync(0xffffffffu, p, off, 16);
        q += __shfl_down_sync(0xffffffffu, q, off, 16);
    }
    if (c == 0) { g_als2[r] = p; g_ald2[r] = q; }
}

// ---------------- layer 2: aggregation, 16-lane group per dst node ----------------
__global__ void k_agg2(const float* __restrict__ b2, float* __restrict__ out) {
    int t = threadIdx.x;
    int d = blockIdx.x * 16 + (t >> 4);
    if (d >= NN) return;
    int c = t & 15;
    unsigned hm = 0xFFFFu << (t & 16);
    int beg = g_off[d], end = g_off[d + 1];
    float ald = g_ald2[d];
    float acc = 0.f, den = 0.f;
    for (int i0 = beg; i0 < end; i0 += 16) {
        int i = i0 + c;
        int s = (i < end) ? g_csr[i] : 0;
        int lim = min(16, end - i0);
#pragma unroll 8
        for (int j = 0; j < lim; j++) {
            int sj = __shfl_sync(hm, s, j, 16);
            float al = g_als2[sj] + ald;
            al = al > 0.f ? al : NEG_SLOPE * al;
            float w = __expf(al);
            den += w;
            acc = fmaf(w, g_h2[sj * OUTC + c], acc);
        }
    }
    out[d * OUTC + c] = acc / den + b2[c];
}

// ---------------- launch ----------------
extern "C" void kernel_launch(void* const* d_in, const int* in_sizes, int n_in,
                              void* d_out, int out_size) {
    const float* x   = (const float*)d_in[0];
    const int*   ei  = (const int*)d_in[1];
    const float* W1  = (const float*)d_in[2];
    const float* as1 = (const float*)d_in[3];
    const float* ad1 = (const float*)d_in[4];
    const float* b1  = (const float*)d_in[5];
    const float* W2  = (const float*)d_in[6];
    const float* as2 = (const float*)d_in[7];
    const float* ad2 = (const float*)d_in[8];
    const float* b2  = (const float*)d_in[9];
    float* out = (float*)d_out;

    k_zero<<<(NN + 255) / 256, 256>>>();
    k_hist<<<(EE / 4 + 255) / 256, 256>>>(ei);
    k_scan<<<1, 1024>>>();
    k_fill<<<(EE / 4 + 255) / 256, 256>>>(ei);
    k_gemm1<<<NN / 8, 128>>>(x, W1, as1, ad1);
    k_agg1<<<(NN + 7) / 8, 256>>>(b1);
    k_gemm2<<<(NN + 15) / 16, 256>>>(W2, as2, ad2);
    k_agg2<<<(NN + 15) / 16, 256>>>(b2, out);
}

// round 7
// speedup vs baseline: 2.5209x; 1.0415x over previous
#include <cuda_runtime.h>
#include <cuda_fp16.h>
#include <math.h>

#define NN 50000
#define EE 800000
#define ET 850000
#define F1 128
#define HEADS 8
#define HID 16
#define OUTC 16
#define NEG_SLOPE 0.2f

// ---------------- scratch ----------------
__device__ __align__(16) __half g_h1h[NN * F1];   // layer1 features, fp16 (gathered)
__device__ __align__(16) float  g_out1[NN * F1];  // layer1 output (fp32, linear reads)
__device__ float g_als1[NN * HEADS];
__device__ float g_ald1[NN * HEADS];
__device__ __align__(16) __half g_h2h[NN * OUTC]; // layer2 features, fp16 (gathered)
__device__ float g_als2[NN];
__device__ float g_ald2[NN];
__device__ int   g_cnt[NN];
__device__ int   g_off[NN + 1];
__device__ int   g_cur[NN];
__device__ int   g_csr[ET];

// ---------------- CSR build ----------------
__global__ void k_zero() {
    int i = blockIdx.x * blockDim.x + threadIdx.x;
    if (i < NN) g_cnt[i] = 1;            // self loop pre-counted
}

__global__ void k_hist(const int* __restrict__ ei) {
    int i = blockIdx.x * blockDim.x + threadIdx.x;
    if (i >= EE / 4) return;
    int4 d4 = ((const int4*)(ei + EE))[i];
    atomicAdd(&g_cnt[d4.x], 1);
    atomicAdd(&g_cnt[d4.y], 1);
    atomicAdd(&g_cnt[d4.z], 1);
    atomicAdd(&g_cnt[d4.w], 1);
}

__global__ void k_scan() {
    const int CH = (NN + 1023) / 1024;
    int t = threadIdx.x;
    int base = t * CH;
    int sum = 0;
    for (int i = 0; i < CH; i++) {
        int idx = base + i;
        if (idx < NN) sum += g_cnt[idx];
    }
    __shared__ int ps[1024];
    ps[t] = sum;
    __syncthreads();
    for (int off = 1; off < 1024; off <<= 1) {
        int v = (t >= off) ? ps[t - off] : 0;
        __syncthreads();
        ps[t] += v;
        __syncthreads();
    }
    int run = ps[t] - sum;
    for (int i = 0; i < CH; i++) {
        int idx = base + i;
        if (idx < NN) {
            g_off[idx] = run;
            g_csr[run] = idx;            // self loop in slot 0
            g_cur[idx] = run + 1;
            run += g_cnt[idx];
        }
    }
    if (t == 1023) g_off[NN] = ps[1023];
}

__global__ void k_fill(const int* __restrict__ ei) {
    int base = (blockIdx.x * blockDim.x + threadIdx.x) * 4;
    if (base >= EE) return;
#pragma unroll
    for (int k = 0; k < 4; k++) {
        int e = base + k;
        if (e < EE) {
            int s = ei[e], d = ei[EE + e];
            int pos = atomicAdd(&g_cur[d], 1);
            g_csr[pos] = s;
        }
    }
}

// ---------------- layer 1: GEMM (8 nodes/block) + fused logits ----------------
__global__ void k_gemm1(const float* __restrict__ x, const float* __restrict__ W1,
                        const float* __restrict__ as1, const float* __restrict__ ad1) {
    int nb = blockIdx.x * 8;
    int t = threadIdx.x;                 // 128
    __shared__ float4 xs[8][32];
    const float4* xv = (const float4*)(x + nb * F1);
    ((float4*)xs)[t]       = xv[t];
    ((float4*)xs)[t + 128] = xv[t + 128];
    __syncthreads();
    float acc[8] = {0.f,0.f,0.f,0.f,0.f,0.f,0.f,0.f};
#pragma unroll 4
    for (int k4 = 0; k4 < 32; k4++) {
        float w0 = W1[(k4 * 4 + 0) * F1 + t];
        float w1 = W1[(k4 * 4 + 1) * F1 + t];
        float w2 = W1[(k4 * 4 + 2) * F1 + t];
        float w3 = W1[(k4 * 4 + 3) * F1 + t];
#pragma unroll
        for (int j = 0; j < 8; j++) {
            float4 xj = xs[j][k4];
            acc[j] = fmaf(xj.x, w0, acc[j]);
            acc[j] = fmaf(xj.y, w1, acc[j]);
            acc[j] = fmaf(xj.z, w2, acc[j]);
            acc[j] = fmaf(xj.w, w3, acc[j]);
        }
    }
    float as = as1[t], ad = ad1[t];
#pragma unroll
    for (int j = 0; j < 8; j++) {
        g_h1h[(nb + j) * F1 + t] = __float2half(acc[j]);
        float p = acc[j] * as, q = acc[j] * ad;
#pragma unroll
        for (int off = 8; off >= 1; off >>= 1) {
            p += __shfl_down_sync(0xffffffffu, p, off, 16);
            q += __shfl_down_sync(0xffffffffu, q, off, 16);
        }
        if ((t & 15) == 0) {
            g_als1[(nb + j) * HEADS + (t >> 4)] = p;
            g_ald1[(nb + j) * HEADS + (t >> 4)] = q;
        }
    }
}

// ---------------- layer 1: aggregation, one WARP per dst node, fp16 gathers ----------------
// lane l owns channels [4l, 4l+4); head h = l>>2
__global__ void k_agg1(const float* __restrict__ b1) {
    int warp = threadIdx.x >> 5;
    int lane = threadIdx.x & 31;
    int d = blockIdx.x * 8 + warp;
    if (d >= NN) return;
    int h = lane >> 2;
    int beg = g_off[d], end = g_off[d + 1];
    float ald = g_ald1[d * HEADS + h];
    float4 acc = {0.f, 0.f, 0.f, 0.f};
    float den = 0.f;
    for (int i0 = beg; i0 < end; i0 += 32) {
        int i = i0 + lane;
        int s = (i < end) ? g_csr[i] : 0;
        int lim = min(32, end - i0);
#pragma unroll 8
        for (int j = 0; j < lim; j++) {
            int sj = __shfl_sync(0xffffffffu, s, j);
            float al = g_als1[sj * HEADS + h] + ald;
            al = al > 0.f ? al : NEG_SLOPE * al;
            float w = __expf(al);
            den += w;
            uint2 hv = *(const uint2*)(g_h1h + sj * F1 + lane * 4);
            float2 f0 = __half22float2(*(const __half2*)&hv.x);
            float2 f1 = __half22float2(*(const __half2*)&hv.y);
            acc.x = fmaf(w, f0.x, acc.x);
            acc.y = fmaf(w, f0.y, acc.y);
            acc.z = fmaf(w, f1.x, acc.z);
            acc.w = fmaf(w, f1.y, acc.w);
        }
    }
    float inv = 1.f / den;
    float4 bv = *(const float4*)(b1 + lane * 4);
    float4 o;
    o.x = acc.x * inv + bv.x;
    o.y = acc.y * inv + bv.y;
    o.z = acc.z * inv + bv.z;
    o.w = acc.w * inv + bv.w;
    o.x = o.x > 0.f ? o.x : expm1f(o.x);
    o.y = o.y > 0.f ? o.y : expm1f(o.y);
    o.z = o.z > 0.f ? o.z : expm1f(o.z);
    o.w = o.w > 0.f ? o.w : expm1f(o.w);
    *(float4*)(g_out1 + d * F1 + lane * 4) = o;
}

// ---------------- layer 2: GEMM, 16 rows/block, smem-staged rows ----------------
__global__ void k_gemm2(const float* __restrict__ W2,
                        const float* __restrict__ as2, const float* __restrict__ ad2) {
    int t = threadIdx.x;
    int rbase = blockIdx.x * 16;
    __shared__ float4 sh[16][32];        // 8KB
    __shared__ float ws[F1][OUTC];       // 8KB
    const float4* src = (const float4*)(g_out1 + rbase * F1);
    ((float4*)sh)[t]       = src[t];
    ((float4*)sh)[t + 256] = src[t + 256];
#pragma unroll
    for (int i = t; i < F1 * OUTC; i += 256) ws[i >> 4][i & 15] = W2[i];
    __syncthreads();
    int r_loc = t >> 4, c = t & 15;
    float acc = 0.f;
#pragma unroll 8
    for (int k4 = 0; k4 < 32; k4++) {
        float4 hv = sh[r_loc][k4];
        acc = fmaf(hv.x, ws[k4 * 4 + 0][c], acc);
        acc = fmaf(hv.y, ws[k4 * 4 + 1][c], acc);
        acc = fmaf(hv.z, ws[k4 * 4 + 2][c], acc);
        acc = fmaf(hv.w, ws[k4 * 4 + 3][c], acc);
    }
    int r = rbase + r_loc;
    g_h2h[r * OUTC + c] = __float2half(acc);
    float p = acc * as2[c], q = acc * ad2[c];
#pragma unroll
    for (int off = 8; off >= 1; off >>= 1) {
        p += __shfl_down_sync(0xffffffffu, p, off, 16);
        q += __shfl_down_sync(0xffffffffu, q, off, 16);
    }
    if (c == 0) { g_als2[r] = p; g_ald2[r] = q; }
}

// ---------------- layer 2: aggregation, 16-lane group per dst node ----------------
__global__ void k_agg2(const float* __restrict__ b2, float* __restrict__ out) {
    int t = threadIdx.x;
    int d = blockIdx.x * 16 + (t >> 4);
    if (d >= NN) return;
    int c = t & 15;
    unsigned hm = 0xFFFFu << (t & 16);
    int beg = g_off[d], end = g_off[d + 1];
    float ald = g_ald2[d];
    float acc = 0.f, den = 0.f;
    for (int i0 = beg; i0 < end; i0 += 16) {
        int i = i0 + c;
        int s = (i < end) ? g_csr[i] : 0;
        int lim = min(16, end - i0);
#pragma unroll 8
        for (int j = 0; j < lim; j++) {
            int sj = __shfl_sync(hm, s, j, 16);
            float al = g_als2[sj] + ald;
            al = al > 0.f ? al : NEG_SLOPE * al;
            float w = __expf(al);
            den += w;
            acc = fmaf(w, __half2float(g_h2h[sj * OUTC + c]), acc);
        }
    }
    out[d * OUTC + c] = acc / den + b2[c];
}

// ---------------- launch ----------------
extern "C" void kernel_launch(void* const* d_in, const int* in_sizes, int n_in,
                              void* d_out, int out_size) {
    const float* x   = (const float*)d_in[0];
    const int*   ei  = (const int*)d_in[1];
    const float* W1  = (const float*)d_in[2];
    const float* as1 = (const float*)d_in[3];
    const float* ad1 = (const float*)d_in[4];
    const float* b1  = (const float*)d_in[5];
    const float* W2  = (const float*)d_in[6];
    const float* as2 = (const float*)d_in[7];
    const float* ad2 = (const float*)d_in[8];
    const float* b2  = (const float*)d_in[9];
    float* out = (float*)d_out;

    k_zero<<<(NN + 255) / 256, 256>>>();
    k_hist<<<(EE / 4 + 255) / 256, 256>>>(ei);
    k_scan<<<1, 1024>>>();
    k_fill<<<(EE / 4 + 255) / 256, 256>>>(ei);
    k_gemm1<<<NN / 8, 128>>>(x, W1, as1, ad1);
    k_agg1<<<(NN + 7) / 8, 256>>>(b1);
    k_gemm2<<<(NN + 15) / 16, 256>>>(W2, as2, ad2);
    k_agg2<<<(NN + 15) / 16, 256>>>(b2, out);
}